// round 9
// baseline (speedup 1.0000x reference)
#include <cuda_runtime.h>

#define B_  4
#define L_  4096
#define H_  16
#define D_  128
#define C_  64
#define NC_ 64
#define GATING_Cf 8.0f

// Scratch (allocation-free rule: __device__ globals)
__device__ float g_final_h[B_ * NC_ * H_ * 2 * D_];   // (b,nc,h,s,d)
__device__ float g_total_A[B_ * NC_ * H_ * 4];        // (b,nc,h,{a00,a01,a10,a11})
__device__ float g_u[B_ * NC_ * H_ * C_ * 2];         // (b,nc,h,t,{u0,u1})
__device__ float g_c[B_ * NC_ * H_ * C_ * 2];         // (b,nc,h,t,{c0,c1})

// ---- f32x2 packed-math helpers (FFMA2: PTX-only on sm_103a) ----
typedef unsigned long long u64t;
__device__ __forceinline__ u64t pk2(float lo, float hi) {
    u64t r; asm("mov.b64 %0,{%1,%2};" : "=l"(r) : "f"(lo), "f"(hi)); return r;
}
__device__ __forceinline__ float2 up2(u64t v) {
    float2 f; asm("mov.b64 {%0,%1},%2;" : "=f"(f.x), "=f"(f.y) : "l"(v)); return f;
}
__device__ __forceinline__ u64t ffma2(u64t a, u64t b, u64t c) {
    u64t d; asm("fma.rn.f32x2 %0,%1,%2,%3;" : "=l"(d) : "l"(a), "l"(b), "l"(c)); return d;
}
__device__ __forceinline__ u64t fmul2(u64t a, u64t b) {
    u64t d; asm("mul.rn.f32x2 %0,%1,%2;" : "=l"(d) : "l"(a), "l"(b)); return d;
}

// ---------------------------------------------------------------------------
// Per-timestep scalar precompute for 8 heads (intra role, 256 threads).
// sA[wi*64+t] = {a11, a12, beta, beta*dt*v0}; sC1[wi*64+t] = beta*dt*v1
// ---------------------------------------------------------------------------
__device__ __forceinline__ void precompute_scalars8(
    int b, int nc, int hbase,
    const float* __restrict__ alpha, const float* __restrict__ omega,
    const float* __restrict__ dt,    const float* __restrict__ beta,
    const float* __restrict__ rg,    const float* __restrict__ V,
    float4* sA, float* sC1)
{
    for (int q = threadIdx.x; q < 8 * C_; q += 256) {
        int wi = q >> 6;
        int t  = q & 63;
        int h  = hbase + wi;
        int l  = nc * C_ + t;
        int idx = (b * L_ + l) * H_ + h;

        float al  = alpha[idx];
        float om  = omega[idx];
        float dtt = dt[idx];
        float be  = beta[idx];
        float r   = rg[idx];

        float tau = 0.5f * dtt;
        float ta  = tau * al;
        float to  = tau * om;
        float opa = 1.0f + ta;
        float oma = 1.0f - ta;
        float to2 = to * to;

        float den   = opa * opa + to2 + 1e-6f;
        float invd  = 1.0f / den;
        float a11   = (opa * oma - to2) * invd;
        float a12   = 2.0f * to * invd;

        float numer = oma * oma + to2;
        float den_e = opa * opa + to2;
        float eig   = numer / (den_e + 1e-6f);
        float expo  = (GATING_Cf * r - 1.0f) * 0.5f;
        float scale = exp2f(expo * __log2f(fmaxf(eig, 1e-8f)));
        a11 *= scale;
        a12 *= scale;

        float v0  = V[idx * 2 + 0];
        float v1  = V[idx * 2 + 1];
        float bdt = be * dtt;

        sA[q]  = make_float4(a11, a12, be, bdt * v0);
        sC1[q] = bdt * v1;
    }
}

// ---------------------------------------------------------------------------
// Intra role: 8 warps, one (b,nc,h) per warp; lane owns 4 d (2x f32x2).
// Emits final_h, total_A, u scalars, c scalars.
// ---------------------------------------------------------------------------
__device__ void intra_role(
    int b, int blk,
    const float* __restrict__ alpha, const float* __restrict__ omega,
    const float* __restrict__ dt,    const float* __restrict__ K,
    const float* __restrict__ V,     const float* __restrict__ beta,
    const float* __restrict__ rg,
    float4* sA, float* sC1, float2 (*sU)[C_])
{
    int hg2   = blk & 1;
    int nc    = blk >> 1;
    int hbase = hg2 * 8;

    precompute_scalars8(b, nc, hbase, alpha, omega, dt, beta, rg, V, sA, sC1);
    __syncthreads();

    // export c scalars (coalesced: one float4 per thread = 2 timesteps)
    {
        int hi = threadIdx.x >> 5;
        int t2 = (threadIdx.x & 31) * 2;
        float4 cv = make_float4(sA[hi * C_ + t2].x,     sA[hi * C_ + t2].y,
                                sA[hi * C_ + t2 + 1].x, sA[hi * C_ + t2 + 1].y);
        int basef4 = ((((b * NC_ + nc) * H_ + hbase) * C_) * 2) >> 2;
        ((float4*)g_c)[basef4 + threadIdx.x] = cv;
    }

    int wi   = threadIdx.x >> 5;
    int lane = threadIdx.x & 31;
    int h    = hbase + wi;
    bool lo16 = (lane < 16);

    u64t S0a = 0, S0b = 0, S1a = 0, S1b = 0;
    float Ax = 1.f, Ay = 0.f;

    const float4* Kp = (const float4*)K + ((b * L_ + nc * C_) * H_ + h) * (D_ / 4) + lane;
    const int kstride = H_ * (D_ / 4);

    #pragma unroll 4
    for (int t = 0; t < C_; t++) {
        float4 kv = Kp[t * kstride];
        float4 sc = sA[wi * C_ + t];
        float  c1 = sC1[wi * C_ + t];

        u64t k01 = pk2(kv.x, kv.y);
        u64t k23 = pk2(kv.z, kv.w);

        float2 q0 = up2(ffma2(S0a, k01, fmul2(S0b, k23)));
        float2 q1 = up2(ffma2(S1a, k01, fmul2(S1b, k23)));
        float p0 = q0.x + q0.y;
        float p1 = q1.x + q1.y;

        float xa = __shfl_xor_sync(0xffffffffu, p0, 16);
        float xb = __shfl_xor_sync(0xffffffffu, p1, 16);
        float m  = lo16 ? (p0 + xa) : (p1 + xb);
        m += __shfl_xor_sync(0xffffffffu, m, 8);
        m += __shfl_xor_sync(0xffffffffu, m, 4);
        m += __shfl_xor_sync(0xffffffffu, m, 2);
        m += __shfl_xor_sync(0xffffffffu, m, 1);
        float other = __shfl_xor_sync(0xffffffffu, m, 16);
        float tot0 = lo16 ? m : other;
        float tot1 = lo16 ? other : m;

        float bd0 = sc.x * tot0 + sc.y * tot1;
        float bd1 = sc.x * tot1 - sc.y * tot0;
        float u0  = sc.w - sc.z * bd0;
        float u1  = c1   - sc.z * bd1;

        u64t cx2  = pk2(sc.x,  sc.x);
        u64t cy2  = pk2(sc.y,  sc.y);
        u64t ncy2 = pk2(-sc.y, -sc.y);
        u64t u02  = pk2(u0, u0);
        u64t u12  = pk2(u1, u1);

        u64t oS0a = S0a, oS0b = S0b;
        S0a = ffma2(cx2, S0a, ffma2(cy2, S1a, fmul2(u02, k01)));
        S0b = ffma2(cx2, S0b, ffma2(cy2, S1b, fmul2(u02, k23)));
        S1a = ffma2(cx2, S1a, ffma2(ncy2, oS0a, fmul2(u12, k01)));
        S1b = ffma2(cx2, S1b, ffma2(ncy2, oS0b, fmul2(u12, k23)));

        float nAx = sc.x * Ax - sc.y * Ay;
        float nAy = sc.x * Ay + sc.y * Ax;
        Ax = nAx; Ay = nAy;

        if (lane == 0) sU[wi][t] = make_float2(u0, u1);
    }

    float2 s0a = up2(S0a), s0b = up2(S0b), s1a = up2(S1a), s1b = up2(S1b);
    int base = (((b * NC_ + nc) * H_ + h) * 2) * D_;
    ((float4*)&g_final_h[base])[lane]      = make_float4(s0a.x, s0a.y, s0b.x, s0b.y);
    ((float4*)&g_final_h[base + D_])[lane] = make_float4(s1a.x, s1a.y, s1b.x, s1b.y);
    if (lane == 0)
        ((float4*)g_total_A)[(b * NC_ + nc) * H_ + h] = make_float4(Ax, Ay, -Ay, Ax);

    __syncwarp();
    float4* ug = (float4*)&g_u[(((b * NC_ + nc) * H_ + h) * C_) * 2];
    ug[lane] = ((const float4*)sU[wi])[lane];
}

// ---------------------------------------------------------------------------
// Full role: 8 warps = 4 heads x 2 d-halves; lane owns 2 complex components.
// z_t = c_t o z_{t-1} + u_t k_t, z_0 = chunk entering state; Y row t = z_t.
// ---------------------------------------------------------------------------
__device__ void full_role(
    int b, int blk,
    const float* __restrict__ K, const float* __restrict__ states,
    float* __restrict__ Y,
    float2* sC, float2* sU)
{
    int hg    = blk & 3;
    int nc    = blk >> 2;
    int hbase = hg * 4;

    // cooperative smem fill: threads 0-127 load u, threads 128-255 load c
    if (threadIdx.x < 128) {
        const float4* ug = (const float4*)&g_u[(((b * NC_ + nc) * H_ + hbase) * C_) * 2];
        float4 v = ug[threadIdx.x];
        int hi = threadIdx.x >> 5;
        int t2 = (threadIdx.x & 31) * 2;
        sU[hi * C_ + t2]     = make_float2(v.x, v.y);
        sU[hi * C_ + t2 + 1] = make_float2(v.z, v.w);
    } else {
        int q = threadIdx.x - 128;
        const float4* cg = (const float4*)&g_c[(((b * NC_ + nc) * H_ + hbase) * C_) * 2];
        float4 v = cg[q];
        int hi = q >> 5;
        int t2 = (q & 31) * 2;
        sC[hi * C_ + t2]     = make_float2(v.x, v.y);
        sC[hi * C_ + t2 + 1] = make_float2(v.z, v.w);
    }
    __syncthreads();

    int w    = threadIdx.x >> 5;
    int lane = threadIdx.x & 31;
    int hi   = w >> 1;
    int h    = hbase + hi;
    int dh   = (w & 1) * 64;
    int ci   = hi * C_;

    int sb = (((b * NC_ + nc) * H_ + h) * 2) * D_ + dh + lane * 2;
    float2 z0 = *(const float2*)&states[sb];
    float2 z1 = *(const float2*)&states[sb + D_];

    const float2* Kp2 = (const float2*)(K + ((b * L_ + nc * C_) * H_ + h) * D_ + dh) + lane;
    const int ks2 = H_ * (D_ / 2);
    float2* Yp0 = (float2*)(Y + (((b * L_ + nc * C_) * H_ + h) * 2) * D_ + dh) + lane;
    float2* Yp1 = Yp0 + D_ / 2;
    const int ys2 = H_ * 2 * (D_ / 2);

    #pragma unroll 4
    for (int t = 0; t < C_; t++) {
        float2 kv = __ldcs(&Kp2[t * ks2]);
        float2 c  = sC[ci + t];
        float2 u  = sU[ci + t];

        float o0x = z0.x, o0y = z0.y;
        z0.x = fmaf(c.x, z0.x, fmaf(c.y, z1.x, u.x * kv.x));
        z0.y = fmaf(c.x, z0.y, fmaf(c.y, z1.y, u.x * kv.y));
        z1.x = fmaf(c.x, z1.x, fmaf(-c.y, o0x, u.y * kv.x));
        z1.y = fmaf(c.x, z1.y, fmaf(-c.y, o0y, u.y * kv.y));

        __stcs(&Yp0[t * ys2], z0);
        __stcs(&Yp1[t * ys2], z1);
    }
}

// ---------------------------------------------------------------------------
// Combo kernel: blocks [0,nfull) run full_role(bf), rest run intra_role(bi).
// ---------------------------------------------------------------------------
__global__ __launch_bounds__(256, 4)
void k_combo(const float* __restrict__ alpha, const float* __restrict__ omega,
             const float* __restrict__ dt,    const float* __restrict__ K,
             const float* __restrict__ V,     const float* __restrict__ beta,
             const float* __restrict__ rg,    const float* __restrict__ states,
             float* __restrict__ Y,
             int bf, int bi, int nfull)
{
    __shared__ float4 sA[8 * C_];
    __shared__ float  sC1[8 * C_];
    __shared__ float2 sU[8][C_];

    if ((int)blockIdx.x < nfull) {
        // reuse sA region as sC/sU for the full role
        full_role(bf, blockIdx.x, K, states, Y,
                  (float2*)sA, (float2*)(sA + 4 * C_ / 2));
    } else {
        intra_role(bi, blockIdx.x - nfull, alpha, omega, dt, K, V, beta, rg,
                   sA, sC1, sU);
    }
}

// ---------------------------------------------------------------------------
// Inter-chunk serial scan for ONE batch. Grid = H_ blocks, 128 threads (=d).
// Emits the PRE-update state (state entering chunk nc).
// ---------------------------------------------------------------------------
__global__ __launch_bounds__(128)
void k_inter(float* __restrict__ out_states, int b)
{
    int h = blockIdx.x;
    int d = threadIdx.x;

    float s0 = 0.f, s1 = 0.f;

    float4 a  = ((const float4*)g_total_A)[(b * NC_ + 0) * H_ + h];
    int fb    = (((b * NC_ + 0) * H_ + h) * 2) * D_;
    float f0  = g_final_h[fb + d];
    float f1  = g_final_h[fb + D_ + d];

    for (int nc = 0; nc < NC_; nc++) {
        float4 an = make_float4(0.f, 0.f, 0.f, 0.f);
        float f0n = 0.f, f1n = 0.f;
        if (nc + 1 < NC_) {
            an = ((const float4*)g_total_A)[(b * NC_ + nc + 1) * H_ + h];
            int fb2 = (((b * NC_ + nc + 1) * H_ + h) * 2) * D_;
            f0n = g_final_h[fb2 + d];
            f1n = g_final_h[fb2 + D_ + d];
        }
        int ob = (((b * NC_ + nc) * H_ + h) * 2) * D_;
        out_states[ob + d]       = s0;
        out_states[ob + D_ + d]  = s1;

        float ns0 = a.x * s0 + a.y * s1 + f0;
        float ns1 = a.z * s0 + a.w * s1 + f1;
        s0 = ns0; s1 = ns1;
        a = an; f0 = f0n; f1 = f1n;
    }
}

// ---------------------------------------------------------------------------
extern "C" void kernel_launch(void* const* d_in, const int* in_sizes, int n_in,
                              void* d_out, int out_size)
{
    const float* alpha = (const float*)d_in[0];
    const float* omega = (const float*)d_in[1];
    const float* dt    = (const float*)d_in[2];
    const float* K     = (const float*)d_in[3];
    const float* V     = (const float*)d_in[4];
    const float* beta  = (const float*)d_in[5];
    const float* rg    = (const float*)d_in[6];

    float* Y      = (float*)d_out;                       // (B,L,H,2,D)
    float* states = Y + (size_t)B_ * L_ * H_ * 2 * D_;   // (B,NC,H,2,D)

    const int NFULL  = NC_ * (H_ / 4);   // 256 full-role blocks per batch
    const int NINTRA = NC_ * (H_ / 8);   // 128 intra-role blocks per batch

    // software pipeline over batches: full(b) overlaps intra(b+1)
    k_combo<<<NINTRA, 256>>>(alpha, omega, dt, K, V, beta, rg, states, Y,
                             -1, 0, 0);
    k_inter<<<H_, 128>>>(states, 0);
    for (int b = 0; b < B_ - 1; b++) {
        k_combo<<<NFULL + NINTRA, 256>>>(alpha, omega, dt, K, V, beta, rg,
                                         states, Y, b, b + 1, NFULL);
        k_inter<<<H_, 128>>>(states, b + 1);
    }
    k_combo<<<NFULL, 256>>>(alpha, omega, dt, K, V, beta, rg, states, Y,
                            B_ - 1, -1, NFULL);
}

// round 10
// speedup vs baseline: 1.8849x; 1.8849x over previous
#include <cuda_runtime.h>

#define B_  4
#define L_  4096
#define H_  16
#define D_  128
#define C_  64
#define NC_ 64
#define GATING_Cf 8.0f

// Scratch (allocation-free rule: __device__ globals)
__device__ float g_final_h[B_ * NC_ * H_ * 2 * D_];   // (b,nc,h,s,d)
__device__ float g_total_A[B_ * NC_ * H_ * 4];        // (b,nc,h,{a00,a01,a10,a11})
__device__ float g_u[B_ * NC_ * H_ * C_ * 2];         // (b,nc,h,t,{u0,u1})
__device__ float g_c[B_ * NC_ * H_ * C_ * 2];         // (b,nc,h,t,{c0,c1})

// ---- f32x2 packed-math helpers (FFMA2: PTX-only on sm_103a) ----
typedef unsigned long long u64t;
__device__ __forceinline__ u64t pk2(float lo, float hi) {
    u64t r; asm("mov.b64 %0,{%1,%2};" : "=l"(r) : "f"(lo), "f"(hi)); return r;
}
__device__ __forceinline__ float2 up2(u64t v) {
    float2 f; asm("mov.b64 {%0,%1},%2;" : "=f"(f.x), "=f"(f.y) : "l"(v)); return f;
}
__device__ __forceinline__ u64t ffma2(u64t a, u64t b, u64t c) {
    u64t d; asm("fma.rn.f32x2 %0,%1,%2,%3;" : "=l"(d) : "l"(a), "l"(b), "l"(c)); return d;
}
__device__ __forceinline__ u64t fmul2(u64t a, u64t b) {
    u64t d; asm("mul.rn.f32x2 %0,%1,%2;" : "=l"(d) : "l"(a), "l"(b)); return d;
}

// ---------------------------------------------------------------------------
// Per-timestep scalar precompute (Cayley discretization + gate modulation).
// sA[wi*64+t] = {a11, a12, beta, beta*dt*v0}; sC1[wi*64+t] = beta*dt*v1
// ---------------------------------------------------------------------------
__device__ __forceinline__ void precompute_scalars(
    int b, int nc, int hbase,
    const float* __restrict__ alpha, const float* __restrict__ omega,
    const float* __restrict__ dt,    const float* __restrict__ beta,
    const float* __restrict__ rg,    const float* __restrict__ V,
    float4* sA, float* sC1)
{
    for (int q = threadIdx.x; q < 4 * C_; q += blockDim.x) {
        int wi = q >> 6;
        int t  = q & 63;
        int h  = hbase + wi;
        int l  = nc * C_ + t;
        int idx = (b * L_ + l) * H_ + h;

        float al  = alpha[idx];
        float om  = omega[idx];
        float dtt = dt[idx];
        float be  = beta[idx];
        float r   = rg[idx];

        float tau = 0.5f * dtt;
        float ta  = tau * al;
        float to  = tau * om;
        float opa = 1.0f + ta;
        float oma = 1.0f - ta;
        float to2 = to * to;

        float den   = opa * opa + to2 + 1e-6f;
        float invd  = 1.0f / den;
        float a11   = (opa * oma - to2) * invd;
        float a12   = 2.0f * to * invd;

        float numer = oma * oma + to2;
        float den_e = opa * opa + to2;
        float eig   = numer / (den_e + 1e-6f);
        float expo  = (GATING_Cf * r - 1.0f) * 0.5f;
        float scale = exp2f(expo * __log2f(fmaxf(eig, 1e-8f)));
        a11 *= scale;
        a12 *= scale;

        float v0  = V[idx * 2 + 0];
        float v1  = V[idx * 2 + 1];
        float bdt = be * dtt;

        sA[q]  = make_float4(a11, a12, be, bdt * v0);
        sC1[q] = bdt * v1;
    }
}

// ---------------------------------------------------------------------------
// K1: intra-chunk scan -> final_h, total_A, u scalars, c scalars.
// One warp per (b,nc,h); lane owns 4 d-slots packed as 2x f32x2.
// ---------------------------------------------------------------------------
__global__ __launch_bounds__(128, 8)
void k_intra(const float* __restrict__ alpha, const float* __restrict__ omega,
             const float* __restrict__ dt,    const float* __restrict__ K,
             const float* __restrict__ V,     const float* __restrict__ beta,
             const float* __restrict__ rg)
{
    __shared__ float4 sA[4 * C_];
    __shared__ float  sC1[4 * C_];
    __shared__ float2 sU[4][C_];

    int blk   = blockIdx.x;          // ((b*NC + nc)*4 + hg)
    int hg    = blk & 3;
    int bn    = blk >> 2;
    int nc    = bn % NC_;
    int b     = bn / NC_;
    int hbase = hg * 4;

    precompute_scalars(b, nc, hbase, alpha, omega, dt, beta, rg, V, sA, sC1);
    __syncthreads();

    // export c scalars for k_full (coalesced: 128 float4 = 4 heads x 64 t)
    {
        int hi = threadIdx.x >> 5;
        int t2 = (threadIdx.x & 31) * 2;
        float4 cv = make_float4(sA[hi * C_ + t2].x,     sA[hi * C_ + t2].y,
                                sA[hi * C_ + t2 + 1].x, sA[hi * C_ + t2 + 1].y);
        int basef4 = ((((b * NC_ + nc) * H_ + hbase) * C_) * 2) >> 2;
        ((float4*)g_c)[basef4 + threadIdx.x] = cv;
    }

    int wi   = threadIdx.x >> 5;
    int lane = threadIdx.x & 31;
    int h    = hbase + wi;
    bool lo16 = (lane < 16);

    u64t S0a = 0, S0b = 0, S1a = 0, S1b = 0;   // packed state (4 d per lane)
    float Ax = 1.f, Ay = 0.f;                  // cumA as complex scalar

    const float4* Kp = (const float4*)K + ((b * L_ + nc * C_) * H_ + h) * (D_ / 4) + lane;
    const int kstride = H_ * (D_ / 4);

    #pragma unroll 4
    for (int t = 0; t < C_; t++) {
        float4 kv = Kp[t * kstride];
        float4 sc = sA[wi * C_ + t];     // {a11, a12, beta, bdt*v0}
        float  c1 = sC1[wi * C_ + t];

        u64t k01 = pk2(kv.x, kv.y);
        u64t k23 = pk2(kv.z, kv.w);

        float2 q0 = up2(ffma2(S0a, k01, fmul2(S0b, k23)));
        float2 q1 = up2(ffma2(S1a, k01, fmul2(S1b, k23)));
        float p0 = q0.x + q0.y;
        float p1 = q1.x + q1.y;

        // folded warp reduction: p0 -> lanes 0-15, p1 -> lanes 16-31
        float xa = __shfl_xor_sync(0xffffffffu, p0, 16);
        float xb = __shfl_xor_sync(0xffffffffu, p1, 16);
        float m  = lo16 ? (p0 + xa) : (p1 + xb);
        m += __shfl_xor_sync(0xffffffffu, m, 8);
        m += __shfl_xor_sync(0xffffffffu, m, 4);
        m += __shfl_xor_sync(0xffffffffu, m, 2);
        m += __shfl_xor_sync(0xffffffffu, m, 1);
        float other = __shfl_xor_sync(0xffffffffu, m, 16);
        float tot0 = lo16 ? m : other;
        float tot1 = lo16 ? other : m;

        // u_t = w_t - beta * (c_t o phi)
        float bd0 = sc.x * tot0 + sc.y * tot1;
        float bd1 = sc.x * tot1 - sc.y * tot0;
        float u0  = sc.w - sc.z * bd0;
        float u1  = c1   - sc.z * bd1;

        u64t cx2  = pk2(sc.x,  sc.x);
        u64t cy2  = pk2(sc.y,  sc.y);
        u64t ncy2 = pk2(-sc.y, -sc.y);
        u64t u02  = pk2(u0, u0);
        u64t u12  = pk2(u1, u1);

        u64t oS0a = S0a, oS0b = S0b;
        S0a = ffma2(cx2, S0a, ffma2(cy2, S1a, fmul2(u02, k01)));
        S0b = ffma2(cx2, S0b, ffma2(cy2, S1b, fmul2(u02, k23)));
        S1a = ffma2(cx2, S1a, ffma2(ncy2, oS0a, fmul2(u12, k01)));
        S1b = ffma2(cx2, S1b, ffma2(ncy2, oS0b, fmul2(u12, k23)));

        float nAx = sc.x * Ax - sc.y * Ay;
        float nAy = sc.x * Ay + sc.y * Ax;
        Ax = nAx; Ay = nAy;

        if (lane == 0) sU[wi][t] = make_float2(u0, u1);
    }

    float2 s0a = up2(S0a), s0b = up2(S0b), s1a = up2(S1a), s1b = up2(S1b);
    int base = (((b * NC_ + nc) * H_ + h) * 2) * D_;
    ((float4*)&g_final_h[base])[lane]      = make_float4(s0a.x, s0a.y, s0b.x, s0b.y);
    ((float4*)&g_final_h[base + D_])[lane] = make_float4(s1a.x, s1a.y, s1b.x, s1b.y);
    if (lane == 0)
        ((float4*)g_total_A)[(b * NC_ + nc) * H_ + h] = make_float4(Ax, Ay, -Ay, Ax);

    __syncwarp();
    // coalesced u writeback: 64 t * 2 floats = 32 float4 per warp
    float4* ug = (float4*)&g_u[(((b * NC_ + nc) * H_ + h) * C_) * 2];
    ug[lane] = ((const float4*)sU[wi])[lane];
}

// ---------------------------------------------------------------------------
// K2: inter-chunk scan, register-tiled. One block per (b,h), thread = d.
// Loads f in tiles of 16 chunks (32 independent loads -> one latency hit
// per tile instead of per chunk). Emits PRE-update state per chunk.
// ---------------------------------------------------------------------------
__global__ __launch_bounds__(128)
void k_inter(float* __restrict__ out_states)
{
    __shared__ float4 sA[NC_];

    int b = blockIdx.x >> 4;
    int h = blockIdx.x & 15;
    int d = threadIdx.x;

    if (threadIdx.x < NC_)
        sA[threadIdx.x] = ((const float4*)g_total_A)[(b * NC_ + threadIdx.x) * H_ + h];
    __syncthreads();

    float s0 = 0.f, s1 = 0.f;

    #pragma unroll
    for (int tile = 0; tile < 4; tile++) {
        float f0[16], f1[16];
        #pragma unroll
        for (int i = 0; i < 16; i++) {
            int fb = (((b * NC_ + tile * 16 + i) * H_ + h) * 2) * D_;
            f0[i] = g_final_h[fb + d];
            f1[i] = g_final_h[fb + D_ + d];
        }
        #pragma unroll
        for (int i = 0; i < 16; i++) {
            int nc = tile * 16 + i;
            int ob = (((b * NC_ + nc) * H_ + h) * 2) * D_;
            out_states[ob + d]      = s0;
            out_states[ob + D_ + d] = s1;
            float4 a = sA[nc];
            float ns0 = a.x * s0 + a.y * s1 + f0[i];
            float ns1 = a.z * s0 + a.w * s1 + f1[i];
            s0 = ns0; s1 = ns1;
        }
    }
}

// ---------------------------------------------------------------------------
// K3: output pass. No scalar recompute: u and c come from k_intra's exports.
// D split across 2 warps per (b,nc,h); lane owns 2 complex components.
// z_t = c_t o z_{t-1} + u_t k_t, z_0 = chunk entering state; Y row t = z_t.
// ---------------------------------------------------------------------------
__global__ __launch_bounds__(256, 7)
void k_full(const float* __restrict__ K, const float* __restrict__ states,
            float* __restrict__ Y)
{
    __shared__ float2 sC[4 * C_];
    __shared__ float2 sU[4 * C_];

    int blk   = blockIdx.x;          // ((b*NC + nc)*4 + hg)
    int hg    = blk & 3;
    int bn    = blk >> 2;
    int nc    = bn % NC_;
    int b     = bn / NC_;
    int hbase = hg * 4;

    // cooperative smem fill: threads 0-127 load u, threads 128-255 load c
    if (threadIdx.x < 128) {
        const float4* ug = (const float4*)&g_u[(((b * NC_ + nc) * H_ + hbase) * C_) * 2];
        float4 v = ug[threadIdx.x];
        int hi = threadIdx.x >> 5;
        int t2 = (threadIdx.x & 31) * 2;
        sU[hi * C_ + t2]     = make_float2(v.x, v.y);
        sU[hi * C_ + t2 + 1] = make_float2(v.z, v.w);
    } else {
        int q = threadIdx.x - 128;
        const float4* cg = (const float4*)&g_c[(((b * NC_ + nc) * H_ + hbase) * C_) * 2];
        float4 v = cg[q];
        int hi = q >> 5;
        int t2 = (q & 31) * 2;
        sC[hi * C_ + t2]     = make_float2(v.x, v.y);
        sC[hi * C_ + t2 + 1] = make_float2(v.z, v.w);
    }
    __syncthreads();

    int w    = threadIdx.x >> 5;
    int lane = threadIdx.x & 31;
    int hi   = w >> 1;               // head within group
    int h    = hbase + hi;
    int dh   = (w & 1) * 64;         // d-half offset
    int ci   = hi * C_;

    // init z = chunk entering state (lane owns 2 complex components)
    int sb = (((b * NC_ + nc) * H_ + h) * 2) * D_ + dh + lane * 2;
    float2 z0 = *(const float2*)&states[sb];
    float2 z1 = *(const float2*)&states[sb + D_];

    const float2* Kp2 = (const float2*)(K + ((b * L_ + nc * C_) * H_ + h) * D_ + dh) + lane;
    const int ks2 = H_ * (D_ / 2);
    float2* Yp0 = (float2*)(Y + (((b * L_ + nc * C_) * H_ + h) * 2) * D_ + dh) + lane;
    float2* Yp1 = Yp0 + D_ / 2;
    const int ys2 = H_ * 2 * (D_ / 2);

    #pragma unroll 4
    for (int t = 0; t < C_; t++) {
        float2 kv = __ldcs(&Kp2[t * ks2]);
        float2 c  = sC[ci + t];
        float2 u  = sU[ci + t];

        float o0x = z0.x, o0y = z0.y;
        z0.x = fmaf(c.x, z0.x, fmaf(c.y, z1.x, u.x * kv.x));
        z0.y = fmaf(c.x, z0.y, fmaf(c.y, z1.y, u.x * kv.y));
        z1.x = fmaf(c.x, z1.x, fmaf(-c.y, o0x, u.y * kv.x));
        z1.y = fmaf(c.x, z1.y, fmaf(-c.y, o0y, u.y * kv.y));

        __stcs(&Yp0[t * ys2], z0);
        __stcs(&Yp1[t * ys2], z1);
    }
}

// ---------------------------------------------------------------------------
extern "C" void kernel_launch(void* const* d_in, const int* in_sizes, int n_in,
                              void* d_out, int out_size)
{
    const float* alpha = (const float*)d_in[0];
    const float* omega = (const float*)d_in[1];
    const float* dt    = (const float*)d_in[2];
    const float* K     = (const float*)d_in[3];
    const float* V     = (const float*)d_in[4];
    const float* beta  = (const float*)d_in[5];
    const float* rg    = (const float*)d_in[6];

    float* Y      = (float*)d_out;                       // (B,L,H,2,D)
    float* states = Y + (size_t)B_ * L_ * H_ * 2 * D_;   // (B,NC,H,2,D)

    k_intra<<<B_ * NC_ * (H_ / 4), 128>>>(alpha, omega, dt, K, V, beta, rg);
    k_inter<<<B_ * H_, 128>>>(states);
    k_full<<<B_ * NC_ * (H_ / 4), 256>>>(K, states, Y);
}